// round 1
// baseline (speedup 1.0000x reference)
#include <cuda_runtime.h>
#include <cstdint>

// Problem shape (fixed by the dataset)
#define BB 4
#define SS 4096
#define DD 512
#define HH 64
#define NROWS (BB * SS)          // 16384
#define QBLOCKS (SS / 64)        // 64 query blocks per batch

typedef unsigned long long ull;

// ---------------- device scratch (no allocs allowed) ----------------
__device__ float g_Q[NROWS * HH];
__device__ float g_K[NROWS * HH];
__device__ float g_V[NROWS * HH];
__device__ float g_A[NROWS * HH];

// ---------------- packed f32x2 helpers (Blackwell FFMA2) ----------------
__device__ __forceinline__ ull ffma2(ull a, ull b, ull c) {
    ull d;
    asm("fma.rn.f32x2 %0, %1, %2, %3;" : "=l"(d) : "l"(a), "l"(b), "l"(c));
    return d;
}
__device__ __forceinline__ ull mul2(ull a, ull b) {
    ull d;
    asm("mul.rn.f32x2 %0, %1, %2;" : "=l"(d) : "l"(a), "l"(b));
    return d;
}
__device__ __forceinline__ ull pack2(float x, float y) {
    ull d;
    asm("mov.b64 %0, {%1, %2};" : "=l"(d) : "f"(x), "f"(y));
    return d;
}
__device__ __forceinline__ float2 unpack2(ull v) {
    float2 r;
    asm("mov.b64 {%0, %1}, %2;" : "=f"(r.x), "=f"(r.y) : "l"(v));
    return r;
}

// =====================================================================
// Kernel 1: QKV projections.  Y = x @ W + b  for W in {Wq, Wk, Wv}.
// Grid: (NROWS/64, 3), 256 threads. 64x64 output tile, BK=32.
// =====================================================================
__global__ __launch_bounds__(256) void qkv_kernel(
    const float* __restrict__ x,
    const float* __restrict__ Wq, const float* __restrict__ bq,
    const float* __restrict__ Wk, const float* __restrict__ bk,
    const float* __restrict__ Wv, const float* __restrict__ bv)
{
    const float* W; const float* bias; float* out;
    if (blockIdx.y == 0)      { W = Wq; bias = bq; out = g_Q; }
    else if (blockIdx.y == 1) { W = Wk; bias = bk; out = g_K; }
    else                      { W = Wv; bias = bv; out = g_V; }

    __shared__ float xs[64 * 32];   // [row][k]
    __shared__ float ws[32 * 64];   // [k][n]

    const int tid = threadIdx.x;
    const int tx = tid & 15;        // 16 cols groups (4 cols each)
    const int ty = tid >> 4;        // 16 row groups (4 rows each)
    const int row0 = blockIdx.x * 64;

    ull acc[4][2];
#pragma unroll
    for (int i = 0; i < 4; ++i) { acc[i][0] = 0ull; acc[i][1] = 0ull; }

    for (int k0 = 0; k0 < DD; k0 += 32) {
        __syncthreads();
        // load x tile 64x32 (coalesced: each warp = one 32-float row segment)
#pragma unroll
        for (int idx = tid; idx < 64 * 32; idx += 256) {
            int r = idx >> 5, c = idx & 31;
            xs[idx] = x[(size_t)(row0 + r) * DD + k0 + c];
        }
        // load W tile 32x64 (coalesced)
#pragma unroll
        for (int idx = tid; idx < 32 * 64; idx += 256) {
            int r = idx >> 6, c = idx & 63;
            ws[idx] = W[(size_t)(k0 + r) * HH + c];
        }
        __syncthreads();

#pragma unroll 8
        for (int kk = 0; kk < 32; ++kk) {
            const ulonglong2 ww = *(const ulonglong2*)&ws[(kk << 6) + (tx << 2)];
#pragma unroll
            for (int i = 0; i < 4; ++i) {
                float a = xs[((ty << 2) + i) * 32 + kk];
                ull ad = pack2(a, a);
                acc[i][0] = ffma2(ad, ww.x, acc[i][0]);
                acc[i][1] = ffma2(ad, ww.y, acc[i][1]);
            }
        }
    }

    const int c0 = tx << 2;
    const float b0 = bias[c0 + 0], b1 = bias[c0 + 1], b2 = bias[c0 + 2], b3 = bias[c0 + 3];
#pragma unroll
    for (int i = 0; i < 4; ++i) {
        float2 p = unpack2(acc[i][0]);
        float2 q = unpack2(acc[i][1]);
        float4 v = make_float4(p.x + b0, p.y + b1, q.x + b2, q.y + b3);
        *(float4*)&out[(size_t)(row0 + (ty << 2) + i) * HH + c0] = v;
    }
}

// =====================================================================
// Kernel 2: causal flash attention (online softmax, never materializes S).
// Grid: 256 CTAs, 256 threads. BM = BN = 64, H = 64.
// Work mapping balances causal load across SMs assuming bid%148 placement.
// =====================================================================
__global__ __launch_bounds__(256) void attn_kernel()
{
    extern __shared__ float smem_f[];
    float* qs  = smem_f;            // 64x64   Q tile (pre-scaled)
    float* kps = smem_f + 4096;     // 64x64   K^T (swizzled) then P tile
    float* vs  = smem_f + 8192;     // 64x64   V tile

    // ---- causal-balanced work mapping ----
    const int bid = blockIdx.x;
    int batch, qb;
    if (bid < 108)      { batch = bid & 3;            qb = bid >> 2; }           // 0..26
    else if (bid < 148) { int t = bid - 108; batch = t & 3; qb = 54 + (t >> 2); } // heavy: 54..63
    else                { int t = bid - 148; batch = t & 3; qb = 53 - (t >> 2); } // 53..27

    const int tid = threadIdx.x;
    const int tx = tid & 15;
    const int ty = tid >> 4;
    const int r0 = ty << 2;         // this thread's 4 query rows within tile
    const int c0 = tx << 2;         // this thread's 4 key cols within tile

    const size_t qbase = ((size_t)batch * SS + (size_t)qb * 64) * HH;
    const float scale = 1.0f / 64.0f;   // 1/sqrt(S), S = 4096

    // load Q tile, pre-scaled
    for (int idx = tid; idx < 4096; idx += 256)
        qs[idx] = g_Q[qbase + idx] * scale;

    ull   o2[4][2];
    float m_i[4], l_i[4];
#pragma unroll
    for (int i = 0; i < 4; ++i) {
        o2[i][0] = 0ull; o2[i][1] = 0ull;
        m_i[i] = -1e30f; l_i[i] = 0.0f;
    }

    for (int j = 0; j <= qb; ++j) {
        __syncthreads();   // protect qs (first iter) / kps,vs reuse
        const size_t kvbase = ((size_t)batch * SS + (size_t)j * 64) * HH;
        // load K transposed+swizzled, V straight (both coalesced from gmem)
        for (int idx = tid; idx < 4096; idx += 256) {
            int kr = idx >> 6, h = idx & 63;
            int col = (((kr >> 2) ^ (h & 15)) << 2) | (kr & 3);
            kps[(h << 6) + col] = g_K[kvbase + idx];
            vs[idx] = g_V[kvbase + idx];
        }
        __syncthreads();

        // S tile = Q @ K^T  (f32x2, conflict-free via swizzle)
        ull s2[4][2];
#pragma unroll
        for (int i = 0; i < 4; ++i) { s2[i][0] = 0ull; s2[i][1] = 0ull; }
#pragma unroll 4
        for (int h = 0; h < 64; ++h) {
            const ulonglong2 kk = *(const ulonglong2*)&kps[(h << 6) + (((tx ^ (h & 15))) << 2)];
#pragma unroll
            for (int i = 0; i < 4; ++i) {
                float q = qs[((r0 + i) << 6) + h];
                ull qd = pack2(q, q);
                s2[i][0] = ffma2(qd, kk.x, s2[i][0]);
                s2[i][1] = ffma2(qd, kk.y, s2[i][1]);
            }
        }

        float sv[4][4];
#pragma unroll
        for (int i = 0; i < 4; ++i) {
            float2 a = unpack2(s2[i][0]);
            float2 b = unpack2(s2[i][1]);
            sv[i][0] = a.x; sv[i][1] = a.y; sv[i][2] = b.x; sv[i][3] = b.y;
        }
        // causal mask on the diagonal block
        if (j == qb) {
#pragma unroll
            for (int i = 0; i < 4; ++i)
#pragma unroll
                for (int jj = 0; jj < 4; ++jj)
                    if (c0 + jj > r0 + i) sv[i][jj] = -1e30f;
        }

        // online softmax update (row reductions across the 16 tx lanes)
#pragma unroll
        for (int i = 0; i < 4; ++i) {
            float mloc = fmaxf(fmaxf(sv[i][0], sv[i][1]), fmaxf(sv[i][2], sv[i][3]));
#pragma unroll
            for (int d = 8; d >= 1; d >>= 1)
                mloc = fmaxf(mloc, __shfl_xor_sync(0xffffffffu, mloc, d));
            float mnew  = fmaxf(m_i[i], mloc);
            float alpha = __expf(m_i[i] - mnew);
            m_i[i] = mnew;
            float psum = 0.0f;
#pragma unroll
            for (int jj = 0; jj < 4; ++jj) {
                sv[i][jj] = __expf(sv[i][jj] - mnew);
                psum += sv[i][jj];
            }
#pragma unroll
            for (int d = 8; d >= 1; d >>= 1)
                psum += __shfl_xor_sync(0xffffffffu, psum, d);
            l_i[i] = l_i[i] * alpha + psum;
            ull av = pack2(alpha, alpha);
            o2[i][0] = mul2(o2[i][0], av);
            o2[i][1] = mul2(o2[i][1], av);
        }

        __syncthreads();   // done reading kps as K^T
        // stash P tile into kps (plain [row][col], float4 stores)
#pragma unroll
        for (int i = 0; i < 4; ++i)
            *(float4*)&kps[((r0 + i) << 6) + c0] =
                make_float4(sv[i][0], sv[i][1], sv[i][2], sv[i][3]);
        __syncthreads();

        // O += P @ V  (f32x2)
#pragma unroll 4
        for (int k = 0; k < 64; ++k) {
            const ulonglong2 vv = *(const ulonglong2*)&vs[(k << 6) + (tx << 2)];
#pragma unroll
            for (int i = 0; i < 4; ++i) {
                float p = kps[((r0 + i) << 6) + k];
                ull pd = pack2(p, p);
                o2[i][0] = ffma2(pd, vv.x, o2[i][0]);
                o2[i][1] = ffma2(pd, vv.y, o2[i][1]);
            }
        }
    }

    // normalize and store attention output (B,S,H)
#pragma unroll
    for (int i = 0; i < 4; ++i) {
        float inv = 1.0f / l_i[i];
        float2 a = unpack2(o2[i][0]);
        float2 b = unpack2(o2[i][1]);
        float4 v = make_float4(a.x * inv, a.y * inv, b.x * inv, b.y * inv);
        *(float4*)&g_A[qbase + (size_t)(r0 + i) * HH + (tx << 2)] = v;
    }
}

// =====================================================================
// Kernel 3: output projection.  out = A @ Wo + bo.  (16384x64)@(64x512)
// Grid: (NROWS/64, 512/128), 256 threads; 64x128 tile, K=64 resident.
// =====================================================================
__global__ __launch_bounds__(256) void proj_kernel(
    const float* __restrict__ Wo, const float* __restrict__ bo,
    float* __restrict__ out)
{
    extern __shared__ float smem_f[];
    float* as  = smem_f;            // 64x64
    float* wos = smem_f + 4096;     // 64x128

    const int tid = threadIdx.x;
    const int tx = tid & 15;        // 16 col groups (8 cols each)
    const int ty = tid >> 4;        // 16 row groups (4 rows each)
    const int row0 = blockIdx.x * 64;
    const int n0 = blockIdx.y * 128;

    for (int idx = tid; idx < 4096; idx += 256)
        as[idx] = g_A[(size_t)row0 * HH + idx];
    for (int idx = tid; idx < 8192; idx += 256) {
        int k = idx >> 7, c = idx & 127;
        wos[idx] = Wo[(size_t)k * DD + n0 + c];
    }
    __syncthreads();

    ull acc[4][4];
#pragma unroll
    for (int i = 0; i < 4; ++i)
#pragma unroll
        for (int jj = 0; jj < 4; ++jj) acc[i][jj] = 0ull;

    const int c0 = tx << 3;
#pragma unroll 8
    for (int k = 0; k < 64; ++k) {
        const ulonglong2 w0 = *(const ulonglong2*)&wos[(k << 7) + c0];
        const ulonglong2 w1 = *(const ulonglong2*)&wos[(k << 7) + c0 + 4];
#pragma unroll
        for (int i = 0; i < 4; ++i) {
            float a = as[((ty << 2) + i) * 64 + k];
            ull ad = pack2(a, a);
            acc[i][0] = ffma2(ad, w0.x, acc[i][0]);
            acc[i][1] = ffma2(ad, w0.y, acc[i][1]);
            acc[i][2] = ffma2(ad, w1.x, acc[i][2]);
            acc[i][3] = ffma2(ad, w1.y, acc[i][3]);
        }
    }

    float bb[8];
#pragma unroll
    for (int jj = 0; jj < 8; ++jj) bb[jj] = bo[n0 + c0 + jj];
#pragma unroll
    for (int i = 0; i < 4; ++i) {
        size_t orow = (size_t)(row0 + (ty << 2) + i) * DD + n0 + c0;
        float2 p0 = unpack2(acc[i][0]);
        float2 p1 = unpack2(acc[i][1]);
        float2 p2 = unpack2(acc[i][2]);
        float2 p3 = unpack2(acc[i][3]);
        *(float4*)&out[orow]     = make_float4(p0.x + bb[0], p0.y + bb[1], p1.x + bb[2], p1.y + bb[3]);
        *(float4*)&out[orow + 4] = make_float4(p2.x + bb[4], p2.y + bb[5], p3.x + bb[6], p3.y + bb[7]);
    }
}

// =====================================================================
extern "C" void kernel_launch(void* const* d_in, const int* in_sizes, int n_in,
                              void* d_out, int out_size)
{
    const float* x  = (const float*)d_in[0];
    const float* Wq = (const float*)d_in[1];
    const float* bq = (const float*)d_in[2];
    const float* Wk = (const float*)d_in[3];
    const float* bk = (const float*)d_in[4];
    const float* Wv = (const float*)d_in[5];
    const float* bv = (const float*)d_in[6];
    const float* Wo = (const float*)d_in[7];
    const float* bo = (const float*)d_in[8];
    float* out = (float*)d_out;

    (void)in_sizes; (void)n_in; (void)out_size;

    qkv_kernel<<<dim3(NROWS / 64, 3), 256>>>(x, Wq, bq, Wk, bk, Wv, bv);
    attn_kernel<<<256, 256, 48 * 1024>>>();
    proj_kernel<<<dim3(NROWS / 64, 4), 256, 48 * 1024>>>(Wo, bo, out);
}